// round 4
// baseline (speedup 1.0000x reference)
#include <cuda_runtime.h>
#include <cuda_bf16.h>
#include <math.h>

#define NN 2048
#define BB 32
#define NSTEPS 10
#define KC 256                 // K chunk
#define NCH (NN / KC)          // 8 chunks
#define SSTR 264               // smem row stride (bf16 elems); 264*2=528B = 33*16 ok for ldsm
#define ROWS_A 32              // CTA M tile
#define ROWS_B 64              // output cols (32 sin + 32 cos batches)
#define BUF_ELEMS ((ROWS_A + ROWS_B) * SSTR)          // per buffer
#define SMEM_BYTES (2 * BUF_ELEMS * 2)                // two bf16 buffers
#define OSTR 65                // sOut fp32 stride

// Persistent scratch (no allocations allowed)
__device__ __align__(16) __nv_bfloat16 g_Kb[NN * NN];    // K in bf16 (constant)
__device__ __align__(16) __nv_bfloat16 g_SCb[64 * NN];   // rows 0-31 sin, 32-63 cos
__device__ __align__(16) float g_theta_fallback[BB * NN];

static __device__ __forceinline__ void cp16(void* dst_smem, const void* src) {
    unsigned d = (unsigned)__cvta_generic_to_shared(dst_smem);
    asm volatile("cp.async.cg.shared.global [%0], [%1], 16;\n" :: "r"(d), "l"(src));
}
static __device__ __forceinline__ void cp_commit() {
    asm volatile("cp.async.commit_group;\n");
}
template <int N>
static __device__ __forceinline__ void cp_wait() {
    asm volatile("cp.async.wait_group %0;\n" :: "n"(N));
}

// ---------------- one-time: K fp32 -> bf16 ----------------
__global__ void __launch_bounds__(256, 1)
k_convK(const float* __restrict__ K) {
    int idx = blockIdx.x * 256 + threadIdx.x;     // over NN*NN/4
    float4 v = ((const float4*)K)[idx];
    __nv_bfloat162 lo, hi;
    lo.x = __float2bfloat16(v.x); lo.y = __float2bfloat16(v.y);
    hi.x = __float2bfloat16(v.z); hi.y = __float2bfloat16(v.w);
    ((__nv_bfloat162*)g_Kb)[idx * 2]     = lo;
    ((__nv_bfloat162*)g_Kb)[idx * 2 + 1] = hi;
}

// ---------------- init: copy theta, seed bf16 sin/cos ----------------
__global__ void __launch_bounds__(256, 1)
k_init(const float* __restrict__ th_in, float* __restrict__ th_buf) {
    int idx = blockIdx.x * 256 + threadIdx.x;
    float th = th_in[idx];
    th_buf[idx] = th;
    float s, c;
    sincosf(th, &s, &c);       // one-time: accurate
    g_SCb[idx]           = __float2bfloat16(s);
    g_SCb[32 * NN + idx] = __float2bfloat16(c);
}

// ---------------- fused step: GEMM (full K) + theta update ------------------
// grid = 64 CTAs: CTA owns rows [bid*32, bid*32+32), all 64 cols, K=2048.
// block = 256 (8 warps): warp w -> mw = w&1 (16 rows), nh = w>>2? no: nh = w>>1 (16 cols)
__global__ void __launch_bounds__(256, 1)
k_step(float* __restrict__ th_io, const float* __restrict__ omega,
       const float* __restrict__ Kg, const float* __restrict__ mu, int last) {
    extern __shared__ __align__(16) char smem_raw[];
    __nv_bfloat16* buf[2];
    buf[0] = (__nv_bfloat16*)smem_raw;
    buf[1] = buf[0] + BUF_ELEMS;

    int tid  = threadIdx.x;
    int lane = tid & 31;
    int w    = tid >> 5;
    int mw   = w & 1;          // m half
    int nh   = w >> 1;         // n quarter (0..3)
    int i0   = blockIdx.x * ROWS_A;

    int g = lane >> 2;         // 0..7
    int t = lane & 3;          // 0..3

    // Async fill of chunk `ch` into buffer `b`.
    // A: 32 rows x 32 uint4; B: 64 rows x 32 uint4  -> 3072 cp / 256 thr = 12 each.
    auto fill = [&](int ch, int b) {
        int k0 = ch * KC;
        __nv_bfloat16* sA = buf[b];
        __nv_bfloat16* sB = buf[b] + ROWS_A * SSTR;
#pragma unroll
        for (int it = 0; it < 12; it++) {
            int idx = it * 256 + tid;
            if (idx < 1024) {
                int row = idx >> 5, c = idx & 31;
                cp16(sA + row * SSTR + c * 8,
                     g_Kb + (size_t)(i0 + row) * NN + k0 + c * 8);
            } else {
                int j = idx - 1024;
                int row = j >> 5, c = j & 31;   // row = output col n (0..63)
                // sin batch n at g_SCb row n; cos batch n-32 at row n  -> uniform
                cp16(sB + row * SSTR + c * 8,
                     g_SCb + (size_t)row * NN + k0 + c * 8);
            }
        }
    };

    float acc[2][4];
#pragma unroll
    for (int nt = 0; nt < 2; nt++)
#pragma unroll
        for (int r = 0; r < 4; r++) acc[nt][r] = 0.f;

    fill(0, 0);
    cp_commit();

    for (int ch = 0; ch < NCH; ch++) {
        if (ch < NCH - 1) {
            fill(ch + 1, (ch + 1) & 1);
            cp_commit();
            cp_wait<1>();
        } else {
            cp_wait<0>();
        }
        __syncthreads();

        __nv_bfloat16* sA = buf[ch & 1];
        __nv_bfloat16* sB = buf[ch & 1] + ROWS_A * SSTR;

#pragma unroll 4
        for (int kk = 0; kk < KC; kk += 16) {
            unsigned a0, a1, a2, a3;
            const __nv_bfloat16* ap =
                sA + (mw * 16 + (lane & 15)) * SSTR + kk + ((lane >> 4) * 8);
            unsigned sa = (unsigned)__cvta_generic_to_shared(ap);
            asm volatile(
                "ldmatrix.sync.aligned.m8n8.x4.shared.b16 {%0,%1,%2,%3}, [%4];"
                : "=r"(a0), "=r"(a1), "=r"(a2), "=r"(a3) : "r"(sa));
#pragma unroll
            for (int nt = 0; nt < 2; nt++) {
                const __nv_bfloat16* p =
                    sB + (nh * 16 + nt * 8 + g) * SSTR + kk + 2 * t;
                unsigned b0 = *(const unsigned*)p;
                unsigned b1 = *(const unsigned*)(p + 8);
                asm volatile(
                    "mma.sync.aligned.m16n8k16.row.col.f32.bf16.bf16.f32 "
                    "{%0,%1,%2,%3}, {%4,%5,%6,%7}, {%8,%9}, {%0,%1,%2,%3};"
                    : "+f"(acc[nt][0]), "+f"(acc[nt][1]),
                      "+f"(acc[nt][2]), "+f"(acc[nt][3])
                    : "r"(a0), "r"(a1), "r"(a2), "r"(a3), "r"(b0), "r"(b1));
            }
        }
        __syncthreads();
    }

    // Exchange accumulators via smem (alias buffer 0): sOut[32 rows][64 cols] fp32
    float* sOut = (float*)smem_raw;
#pragma unroll
    for (int nt = 0; nt < 2; nt++) {
        int col  = nh * 16 + nt * 8 + 2 * t;
        int row0 = mw * 16 + g;
        sOut[row0 * OSTR + col]           = acc[nt][0];
        sOut[row0 * OSTR + col + 1]       = acc[nt][1];
        sOut[(row0 + 8) * OSTR + col]     = acc[nt][2];
        sOut[(row0 + 8) * OSTR + col + 1] = acc[nt][3];
    }
    __syncthreads();

    // Update phase: 1024 (batch,row) pairs / 256 threads = 4 each (consecutive rows)
    float coef = (Kg[0] * (1.0f / NN)) * (mu[0] * 0.5f);
    int bi = tid >> 3;                 // batch 0..31
    int il = (tid * 4) & 31;           // local row, 4 consecutive

    size_t base = (size_t)bi * NN + i0 + il;
    float4 th = *(const float4*)&th_io[base];
    float4 om = *(const float4*)&omega[i0 + il];

    // current sin/cos: exactly the bf16 operands the GEMM consumed
    ushort4 sraw = *(const ushort4*)&g_SCb[base];
    ushort4 craw = *(const ushort4*)&g_SCb[32 * NN + base];

    float thv[4] = {th.x, th.y, th.z, th.w};
    float omv[4] = {om.x, om.y, om.z, om.w};
    unsigned short sv[4] = {sraw.x, sraw.y, sraw.z, sraw.w};
    unsigned short cv[4] = {craw.x, craw.y, craw.z, craw.w};

    float sn[4], cn[4];
#pragma unroll
    for (int q = 0; q < 4; q++) {
        float Ks = sOut[(il + q) * OSTR + bi];
        float Kc = sOut[(il + q) * OSTR + bi + 32];
        float si = __bfloat162float(*(__nv_bfloat16*)&sv[q]);
        float ci = __bfloat162float(*(__nv_bfloat16*)&cv[q]);
        float dth = omv[q] + coef * (ci * Ks - si * Kc);
        thv[q] = fmaf(0.1f, dth, thv[q]);
        if (last) {
            // reference-exact wrap to (-pi, pi] (intermediate wraps are
            // transparent to the dynamics; |theta| stays small over 10 steps)
            float s_, c_;
            sincosf(thv[q], &s_, &c_);
            thv[q] = atan2f(s_, c_);
        } else {
            __sincosf(thv[q], &sn[q], &cn[q]);
        }
    }

    *(float4*)&th_io[base] = make_float4(thv[0], thv[1], thv[2], thv[3]);
    if (!last) {
        __nv_bfloat162 s01 = __floats2bfloat162_rn(sn[0], sn[1]);
        __nv_bfloat162 s23 = __floats2bfloat162_rn(sn[2], sn[3]);
        __nv_bfloat162 c01 = __floats2bfloat162_rn(cn[0], cn[1]);
        __nv_bfloat162 c23 = __floats2bfloat162_rn(cn[2], cn[3]);
        *(__nv_bfloat162*)&g_SCb[base]               = s01;
        *(__nv_bfloat162*)&g_SCb[base + 2]           = s23;
        *(__nv_bfloat162*)&g_SCb[32 * NN + base]     = c01;
        *(__nv_bfloat162*)&g_SCb[32 * NN + base + 2] = c23;
    }
}

// ---------------- coherence (accurate, from final wrapped theta) ------------
__global__ void __launch_bounds__(256, 1)
k_coh(const float* __restrict__ th_buf, float* __restrict__ coh_out) {
    int b = blockIdx.x;
    int tid = threadIdx.x;
    float ss = 0.f, cc = 0.f;
    for (int i = tid; i < NN; i += 256) {
        float s, c;
        sincosf(th_buf[b * NN + i], &s, &c);
        ss += s; cc += c;
    }
    __shared__ float rs[256], rc[256];
    rs[tid] = ss; rc[tid] = cc;
    __syncthreads();
    for (int o = 128; o > 0; o >>= 1) {
        if (tid < o) { rs[tid] += rs[tid + o]; rc[tid] += rc[tid + o]; }
        __syncthreads();
    }
    if (tid == 0) {
        float cm = rc[0] * (1.0f / NN);
        float sm = rs[0] * (1.0f / NN);
        coh_out[b] = sqrtf(cm * cm + sm * sm);
    }
}

extern "C" void kernel_launch(void* const* d_in, const int* in_sizes, int n_in,
                              void* d_out, int out_size) {
    const float* theta = (const float*)d_in[0];
    const float* K     = (const float*)d_in[1];
    const float* omega = (const float*)d_in[2];
    const float* Kg    = (const float*)d_in[3];
    const float* mu    = (const float*)d_in[4];
    float* out = (float*)d_out;

    float* th_buf;
    float* coh_out = nullptr;
    if (out_size >= BB * NN) {
        th_buf = out;
        if (out_size >= BB * NN + BB) coh_out = out + BB * NN;
    } else {
        float* sym;
        cudaGetSymbolAddress((void**)&sym, g_theta_fallback);
        th_buf = sym;
        coh_out = out;
    }

    cudaFuncSetAttribute(k_step, cudaFuncAttributeMaxDynamicSharedMemorySize,
                         SMEM_BYTES);

    k_convK<<<NN * NN / 1024, 256>>>(K);
    k_init<<<(BB * NN) / 256, 256>>>(theta, th_buf);
    for (int t = 0; t < NSTEPS; t++) {
        k_step<<<NN / ROWS_A, 256, SMEM_BYTES>>>(th_buf, omega, Kg, mu,
                                                 t == NSTEPS - 1);
    }
    if (coh_out) k_coh<<<BB, 256>>>(th_buf, coh_out);
}

// round 5
// speedup vs baseline: 1.4759x; 1.4759x over previous
#include <cuda_runtime.h>
#include <cuda_bf16.h>
#include <math.h>

#define NN 2048
#define BB 32
#define NSTEPS 10
#define KSPLIT 8
#define KC 256                // K chunk per CTA
#define MT 128                // rows per CTA
#define CTAS 128
#define THREADS 256
#define SSTR 264              // smem row stride (bf16 elems)
#define SA_ELEMS (MT * SSTR)
#define SB_ELEMS (64 * SSTR)
#define SMEM_BYTES ((SA_ELEMS + SB_ELEMS) * 2)

// Persistent scratch (no allocations allowed)
__device__ __align__(16) __nv_bfloat16 g_SCb[64 * NN];   // rows 0-31 sin, 32-63 cos
__device__ __align__(16) float g_ps[KSPLIT][BB * NN];    // partial K*sin  [b*NN+i]
__device__ __align__(16) float g_pc[KSPLIT][BB * NN];    // partial K*cos
__device__ __align__(16) float2 g_cohP[CTAS];
__device__ __align__(16) float g_theta_fallback[BB * NN];
// barrier state on separate 128B lines
__device__ __align__(128) unsigned g_cnt;
__device__ __align__(128) unsigned g_gen;

static __device__ __forceinline__ void cp16(void* dst_smem, const void* src) {
    unsigned d = (unsigned)__cvta_generic_to_shared(dst_smem);
    asm volatile("cp.async.cg.shared.global [%0], [%1], 16;\n" :: "r"(d), "l"(src));
}
static __device__ __forceinline__ void cp_commit() {
    asm volatile("cp.async.commit_group;\n");
}
static __device__ __forceinline__ void cp_wait0() {
    asm volatile("cp.async.wait_group 0;\n");
}

// Sense-reversing grid barrier. All 128 CTAs are co-resident (grid <= SM count).
// Leader-only L2 atomics; bar.sync + release/acquire fences give cumulativity.
static __device__ __forceinline__ void gbar() {
    __syncthreads();
    if (threadIdx.x == 0) {
        __threadfence();                        // release all CTA writes
        unsigned my = atomicAdd(&g_gen, 0u);    // current generation
        unsigned arr = atomicAdd(&g_cnt, 1u);
        if (arr == CTAS - 1) {
            g_cnt = 0;
            __threadfence();
            atomicAdd(&g_gen, 1u);
        } else {
            while (atomicAdd(&g_gen, 0u) == my) __nanosleep(64);
        }
        __threadfence();                        // acquire
    }
    __syncthreads();
}

__global__ void __launch_bounds__(THREADS, 1)
k_all(const float* __restrict__ theta_in, const float* __restrict__ K,
      const float* __restrict__ omega, const float* __restrict__ Kg,
      const float* __restrict__ mu, float* __restrict__ th_out,
      float* __restrict__ coh_out) {
    extern __shared__ __align__(16) char smem_raw[];
    __nv_bfloat16* sA = (__nv_bfloat16*)smem_raw;        // K tile, resident all steps
    __nv_bfloat16* sB = sA + SA_ELEMS;                   // sin/cos tile, per step

    int tid  = threadIdx.x;
    int lane = tid & 31;
    int w    = tid >> 5;
    int bid  = blockIdx.x;
    int ib   = bid >> 3, ks = bid & 7;
    int i0   = ib * MT, k0 = ks * KC;
    int g    = lane >> 2, t = lane & 3;

    // ---- prologue 1: convert this CTA's fp32 K tile -> bf16 smem (once) ----
    {
        const float* Kt = K + (size_t)i0 * NN + k0;
#pragma unroll 4
        for (int it = 0; it < 32; it++) {
            int idx = it * THREADS + tid;           // 8192 float4 total
            int row = idx >> 6, c = idx & 63;
            float4 v = *(const float4*)(Kt + (size_t)row * NN + c * 4);
            __nv_bfloat162 lo = __floats2bfloat162_rn(v.x, v.y);
            __nv_bfloat162 hi = __floats2bfloat162_rn(v.z, v.w);
            uint2 pk = make_uint2(*(unsigned*)&lo, *(unsigned*)&hi);
            *(uint2*)(sA + row * SSTR + c * 4) = pk;
        }
    }

    // ---- prologue 2: per-thread theta state (2 elements, fixed mapping) ----
    int eidx = (bid * THREADS + tid) * 2;
    int igl  = eidx & (NN - 1);
    float th0 = theta_in[eidx], th1 = theta_in[eidx + 1];
    float om0 = omega[igl],     om1 = omega[igl + 1];
    float coef = (Kg[0] * (1.0f / NN)) * (mu[0] * 0.5f);
    float s0, c0, s1, c1;
    sincosf(th0, &s0, &c0);     // one-time accurate seed
    sincosf(th1, &s1, &c1);
    __nv_bfloat162 sb2 = __floats2bfloat162_rn(s0, s1);
    __nv_bfloat162 cb2 = __floats2bfloat162_rn(c0, c1);
    *(__nv_bfloat162*)&g_SCb[eidx]           = sb2;
    *(__nv_bfloat162*)&g_SCb[32 * NN + eidx] = cb2;
    float si0 = __low2float(sb2), si1 = __high2float(sb2);
    float ci0 = __low2float(cb2), ci1 = __high2float(cb2);

    gbar();

    // ---- 10 steps: MMA phase + update phase ----
    for (int step = 0; step < NSTEPS; step++) {
        // fill B tile: 64 rows x 256 bf16 (sin rows 0-31, cos rows 32-63)
#pragma unroll
        for (int it = 0; it < 8; it++) {
            int idx = it * THREADS + tid;            // 2048 x 16B
            int row = idx >> 5, c = idx & 31;
            cp16(sB + row * SSTR + c * 8,
                 g_SCb + (size_t)row * NN + k0 + c * 8);
        }
        cp_commit();
        cp_wait0();
        __syncthreads();

        float acc[8][4];
#pragma unroll
        for (int nt = 0; nt < 8; nt++)
#pragma unroll
            for (int r = 0; r < 4; r++) acc[nt][r] = 0.f;

#pragma unroll 4
        for (int kk = 0; kk < KC; kk += 16) {
            unsigned a0, a1, a2, a3;
            const __nv_bfloat16* ap =
                sA + (w * 16 + (lane & 15)) * SSTR + kk + ((lane >> 4) * 8);
            unsigned sa = (unsigned)__cvta_generic_to_shared(ap);
            asm volatile(
                "ldmatrix.sync.aligned.m8n8.x4.shared.b16 {%0,%1,%2,%3}, [%4];"
                : "=r"(a0), "=r"(a1), "=r"(a2), "=r"(a3) : "r"(sa));
#pragma unroll
            for (int nt = 0; nt < 8; nt++) {
                const __nv_bfloat16* p = sB + (nt * 8 + g) * SSTR + kk + 2 * t;
                unsigned b0 = *(const unsigned*)p;
                unsigned b1 = *(const unsigned*)(p + 8);
                asm volatile(
                    "mma.sync.aligned.m16n8k16.row.col.f32.bf16.bf16.f32 "
                    "{%0,%1,%2,%3}, {%4,%5,%6,%7}, {%8,%9}, {%0,%1,%2,%3};"
                    : "+f"(acc[nt][0]), "+f"(acc[nt][1]),
                      "+f"(acc[nt][2]), "+f"(acc[nt][3])
                    : "r"(a0), "r"(a1), "r"(a2), "r"(a3), "r"(b0), "r"(b1));
            }
        }

        // store partials: cols 0-31 -> sin partials, 32-63 -> cos
        {
            int irow = i0 + w * 16 + g;
#pragma unroll
            for (int nt = 0; nt < 8; nt++) {
                int col = nt * 8 + 2 * t;
                float* dst = (nt < 4) ? g_ps[ks] : g_pc[ks];
                int cb = col & 31;
                dst[(size_t)cb * NN + irow]           = acc[nt][0];
                dst[(size_t)(cb + 1) * NN + irow]     = acc[nt][1];
                dst[(size_t)cb * NN + irow + 8]       = acc[nt][2];
                dst[(size_t)(cb + 1) * NN + irow + 8] = acc[nt][3];
            }
        }
        gbar();

        // update phase: reduce split-K partials, integrate (theta in regs)
        float ss0 = 0.f, ss1 = 0.f, cs0 = 0.f, cs1 = 0.f;
#pragma unroll
        for (int kq = 0; kq < KSPLIT; kq++) {
            float2 p = *(const float2*)&g_ps[kq][eidx];
            ss0 += p.x; ss1 += p.y;
            float2 q = *(const float2*)&g_pc[kq][eidx];
            cs0 += q.x; cs1 += q.y;
        }
        th0 = fmaf(0.1f, om0 + coef * (ci0 * ss0 - si0 * cs0), th0);
        th1 = fmaf(0.1f, om1 + coef * (ci1 * ss1 - si1 * cs1), th1);

        if (step < NSTEPS - 1) {
            __sincosf(th0, &s0, &c0);   // bf16 rounding dominates intrinsic err
            __sincosf(th1, &s1, &c1);
            sb2 = __floats2bfloat162_rn(s0, s1);
            cb2 = __floats2bfloat162_rn(c0, c1);
            *(__nv_bfloat162*)&g_SCb[eidx]           = sb2;
            *(__nv_bfloat162*)&g_SCb[32 * NN + eidx] = cb2;
            si0 = __low2float(sb2); si1 = __high2float(sb2);
            ci0 = __low2float(cb2); ci1 = __high2float(cb2);
            gbar();
        }
    }

    // ---- epilogue: reference-exact wrap (once), output, coherence ----
    float sn0, cn0, sn1, cn1;
    sincosf(th0, &sn0, &cn0); th0 = atan2f(sn0, cn0);
    sincosf(th1, &sn1, &cn1); th1 = atan2f(sn1, cn1);
    th_out[eidx]     = th0;
    th_out[eidx + 1] = th1;

    if (coh_out) {
        sincosf(th0, &sn0, &cn0);       // trig of wrapped theta (as reference)
        sincosf(th1, &sn1, &cn1);
        float ssP = sn0 + sn1, ccP = cn0 + cn1;
        float* rs = (float*)smem_raw;   // reuse smem as reduce scratch
        float* rc = rs + THREADS;
        __syncthreads();
        rs[tid] = ssP; rc[tid] = ccP;
        __syncthreads();
        for (int o = 128; o > 0; o >>= 1) {
            if (tid < o) { rs[tid] += rs[tid + o]; rc[tid] += rc[tid + o]; }
            __syncthreads();
        }
        if (tid == 0) g_cohP[bid] = make_float2(rs[0], rc[0]);
        gbar();
        if (bid < BB && tid == 0) {
            float ss = 0.f, cc = 0.f;
#pragma unroll
            for (int q = 0; q < 4; q++) {        // batch b spans CTAs 4b..4b+3
                float2 p = g_cohP[bid * 4 + q];
                ss += p.x; cc += p.y;
            }
            float sm = ss * (1.0f / NN), cm = cc * (1.0f / NN);
            coh_out[bid] = sqrtf(cm * cm + sm * sm);
        }
    }
}

extern "C" void kernel_launch(void* const* d_in, const int* in_sizes, int n_in,
                              void* d_out, int out_size) {
    const float* theta = (const float*)d_in[0];
    const float* K     = (const float*)d_in[1];
    const float* omega = (const float*)d_in[2];
    const float* Kg    = (const float*)d_in[3];
    const float* mu    = (const float*)d_in[4];
    float* out = (float*)d_out;

    float* th_buf;
    float* coh_out = nullptr;
    if (out_size >= BB * NN) {
        th_buf = out;
        if (out_size >= BB * NN + BB) coh_out = out + BB * NN;
    } else {
        float* sym;
        cudaGetSymbolAddress((void**)&sym, g_theta_fallback);
        th_buf = sym;
        coh_out = out;
    }

    cudaFuncSetAttribute(k_all, cudaFuncAttributeMaxDynamicSharedMemorySize,
                         SMEM_BYTES);
    k_all<<<CTAS, THREADS, SMEM_BYTES>>>(theta, K, omega, Kg, mu,
                                         th_buf, coh_out);
}